// round 3
// baseline (speedup 1.0000x reference)
#include <cuda_runtime.h>
#include <math.h>
#include <stdint.h>

// Shapes (fixed by the problem)
#define B_SZ  8192
#define S_IN  4096
#define S_OUT 4096
#define H     128

// h2 scratch in bf16x2 (8192 x 64 u32 = 2 MB) — __device__ global, no allocation.
__device__ uint32_t g_h2u[B_SZ * (H / 2)];

// ---------------------------------------------------------------------------
// bf16 helpers
// ---------------------------------------------------------------------------
__device__ __forceinline__ uint32_t f2bf16x2(float e0, float e1) {
    // packed bf16x2 with e0 in low half (element order e0, e1)
    uint32_t r;
    asm("cvt.rn.bf16x2.f32 %0, %1, %2;" : "=r"(r) : "f"(e1), "f"(e0));
    return r;
}
__device__ __forceinline__ uint4 cvt8(float4 a, float4 b) {
    uint4 r;
    r.x = f2bf16x2(a.x, a.y); r.y = f2bf16x2(a.z, a.w);
    r.z = f2bf16x2(b.x, b.y); r.w = f2bf16x2(b.z, b.w);
    return r;
}
// mma.m16n8k16 row.col bf16*bf16 -> f32, D==C accumulate
__device__ __forceinline__ void mma16(float* c, const uint32_t* a, const uint32_t* b) {
    asm volatile(
        "mma.sync.aligned.m16n8k16.row.col.f32.bf16.bf16.f32 "
        "{%0,%1,%2,%3}, {%4,%5,%6,%7}, {%8,%9}, {%0,%1,%2,%3};"
        : "+f"(c[0]), "+f"(c[1]), "+f"(c[2]), "+f"(c[3])
        : "r"(a[0]), "r"(a[1]), "r"(a[2]), "r"(a[3]), "r"(b[0]), "r"(b[1]));
}

// ---------------------------------------------------------------------------
// AR(7) IIR filter body. One thread per batch row; writes ar into out.
// ar[t] = noise[t] + sum_{i=0..6} ar[t-1-i]*c[i]  (t >= 7; zero before).
// Critical path = 1 FMA/step: partials built oldest-first so only the final
// FMA (c0 * y[t-1]) is on the serial chain; lag-k inputs have 4k cyc slack.
// Double-buffered register prefetch of the next 28 noise values.
// ---------------------------------------------------------------------------
__device__ __forceinline__ void ar_row(const float* __restrict__ noise,
                                       const float* __restrict__ coef,
                                       float* __restrict__ out, int r) {
    const float* nr = noise + (size_t)r * S_OUT;
    float* orow = out + (size_t)r * S_OUT;

    float cc[7];
#pragma unroll
    for (int i = 0; i < 7; ++i) cc[i] = __ldg(&coef[i]);

    float y7 = nr[7];                               // ar[7] = noise[7]
    ((float4*)orow)[0] = make_float4(0.f, 0.f, 0.f, 0.f);
    ((float4*)orow)[1] = make_float4(0.f, 0.f, 0.f, y7);

    // hist[i] = y[t-1-i] entering step t (t starts at 8)
    float hist[7] = {y7, 0.f, 0.f, 0.f, 0.f, 0.f, 0.f};

    float4 buf[2][7];
#pragma unroll
    for (int q = 0; q < 7; ++q) buf[0][q] = ((const float4*)(nr + 8))[q];

    // t = 8 .. 4095 : 4088 = 146 * 28 steps
    for (int it = 0; it < 146; ++it) {
        const int cur = it & 1;
        if (it + 1 < 146) {
            const float4* np = (const float4*)(nr + 8 + (it + 1) * 28);
#pragma unroll
            for (int q = 0; q < 7; ++q) buf[cur ^ 1][q] = np[q];
        }
        const float* nv = (const float*)buf[cur];
        float ov[28];
#pragma unroll
        for (int j = 0; j < 28; ++j) {
            float p = nv[j];
            p = fmaf(cc[6], hist[6], p);
            p = fmaf(cc[5], hist[5], p);
            p = fmaf(cc[4], hist[4], p);
            p = fmaf(cc[3], hist[3], p);
            p = fmaf(cc[2], hist[2], p);
            p = fmaf(cc[1], hist[1], p);
            float y = fmaf(cc[0], hist[0], p);      // the only serial FMA
#pragma unroll
            for (int i = 6; i > 0; --i) hist[i] = hist[i - 1];
            hist[0] = y;
            ov[j] = y;
        }
        float4* op = (float4*)(orow + 8 + it * 28);
#pragma unroll
        for (int q = 0; q < 7; ++q) op[q] = ((const float4*)ov)[q];
    }
}

// ---------------------------------------------------------------------------
// MLP front body: h2 = relu(relu(x@W1^T + b1)@W2^T + b2) -> g_h2u
// GEMM1: M=8192 (BM=64/block), N=128, K=4096, BK=32, bf16 mma m16n8k16.
// GEMM2 (K=128) fused: h1 tile stays in smem (bf16).
// 256 threads = 8 warps, warp grid 2(m) x 4(n), warp tile 32x32.
// smem layout (41984 B, units of uint32 = bf16x2):
//   [0,10240)      As[2][64][20]
//   [10240,30720)  Bs[2][128][20]
//   [0,17408)      h1s[64][68]   (reused after GEMM1)
//   [30720,40960)  W2s[128][20]
//   [40960,41984)  b1s[128], b2s[128] (f32)
// ---------------------------------------------------------------------------
__device__ void mlp12_body(unsigned char* smem_raw, int blk,
                           const float* __restrict__ x,
                           const float* __restrict__ W1,
                           const float* __restrict__ b1,
                           const float* __restrict__ W2,
                           const float* __restrict__ b2) {
    uint32_t (*As)[64][20]  = reinterpret_cast<uint32_t(*)[64][20]>(smem_raw);
    uint32_t (*Bs)[128][20] = reinterpret_cast<uint32_t(*)[128][20]>(smem_raw + 10240);
    uint32_t (*h1s)[68]     = reinterpret_cast<uint32_t(*)[68]>(smem_raw);
    uint32_t (*W2s)[20]     = reinterpret_cast<uint32_t(*)[20]>(smem_raw + 30720);
    float* b1s = reinterpret_cast<float*>(smem_raw + 40960);
    float* b2s = b1s + 128;

    const int tid  = threadIdx.x;
    const int warp = tid >> 5, lane = tid & 31;
    const int g    = lane >> 2, tig = lane & 3;
    const int wm0  = (warp >> 2) * 32;   // 0 or 32
    const int wn0  = (warp & 3) * 32;    // 0,32,64,96
    const int bm0  = blk * 64;

    if (tid < 128) { b1s[tid] = b1[tid]; b2s[tid] = b2[tid]; }

    // A loader: 4 threads/row, 8 floats each. B loader: 2 threads/row, 16 floats.
    const int lrowA = tid >> 2;                 // 0..63
    const int lkA   = (tid & 3) * 8;
    const int lkA2  = lkA >> 1;
    const int lrowB = tid >> 1;                 // 0..127
    const int lkB   = (tid & 1) * 16;
    const int lkB2  = lkB >> 1;

    const float* gA = x  + (size_t)(bm0 + lrowA) * S_IN + lkA;
    const float* gB = W1 + (size_t)lrowB * S_IN + lkB;

    float c[2][4][4];
#pragma unroll
    for (int mt = 0; mt < 2; ++mt)
#pragma unroll
        for (int nt = 0; nt < 4; ++nt)
#pragma unroll
            for (int i = 0; i < 4; ++i) c[mt][nt][i] = 0.f;

    // ---- GEMM1 main loop (K = 4096, BK = 32, 128 iters, double buffered) ----
    {
        float4 a0 = *(const float4*)gA;
        float4 a1 = *(const float4*)(gA + 4);
        float4 w0 = *(const float4*)gB;
        float4 w1 = *(const float4*)(gB + 4);
        float4 w2 = *(const float4*)(gB + 8);
        float4 w3 = *(const float4*)(gB + 12);
        *(uint4*)&As[0][lrowA][lkA2]     = cvt8(a0, a1);
        *(uint4*)&Bs[0][lrowB][lkB2]     = cvt8(w0, w1);
        *(uint4*)&Bs[0][lrowB][lkB2 + 4] = cvt8(w2, w3);
    }
    __syncthreads();

    for (int kt = 0; kt < 128; ++kt) {
        const int cur = kt & 1;
        float4 a0, a1, w0, w1, w2, w3;
        if (kt + 1 < 128) {
            const int k0 = (kt + 1) * 32;
            a0 = *(const float4*)(gA + k0);
            a1 = *(const float4*)(gA + k0 + 4);
            w0 = *(const float4*)(gB + k0);
            w1 = *(const float4*)(gB + k0 + 4);
            w2 = *(const float4*)(gB + k0 + 8);
            w3 = *(const float4*)(gB + k0 + 12);
        }
#pragma unroll
        for (int ks = 0; ks < 2; ++ks) {
            const int kb = ks * 8;
            uint32_t a[2][4], bf[4][2];
#pragma unroll
            for (int mt = 0; mt < 2; ++mt) {
                const int m = wm0 + mt * 16 + g;
                a[mt][0] = As[cur][m][kb + tig];
                a[mt][1] = As[cur][m + 8][kb + tig];
                a[mt][2] = As[cur][m][kb + tig + 4];
                a[mt][3] = As[cur][m + 8][kb + tig + 4];
            }
#pragma unroll
            for (int nt = 0; nt < 4; ++nt) {
                const int n = wn0 + nt * 8 + g;
                bf[nt][0] = Bs[cur][n][kb + tig];
                bf[nt][1] = Bs[cur][n][kb + tig + 4];
            }
#pragma unroll
            for (int mt = 0; mt < 2; ++mt)
#pragma unroll
                for (int nt = 0; nt < 4; ++nt) mma16(c[mt][nt], a[mt], bf[nt]);
        }
        if (kt + 1 < 128) {
            const int nb = cur ^ 1;
            *(uint4*)&As[nb][lrowA][lkA2]     = cvt8(a0, a1);
            *(uint4*)&Bs[nb][lrowB][lkB2]     = cvt8(w0, w1);
            *(uint4*)&Bs[nb][lrowB][lkB2 + 4] = cvt8(w2, w3);
        }
        __syncthreads();
    }

    // ---- h1 = relu(c + b1) -> h1s (bf16), overwrites As/Bs (reads done) -----
#pragma unroll
    for (int mt = 0; mt < 2; ++mt)
#pragma unroll
        for (int nt = 0; nt < 4; ++nt) {
            const int row  = wm0 + mt * 16 + g;
            const int col  = wn0 + nt * 8 + 2 * tig;
            const int col2 = col >> 1;
            float v0 = fmaxf(c[mt][nt][0] + b1s[col], 0.f);
            float v1 = fmaxf(c[mt][nt][1] + b1s[col + 1], 0.f);
            float v2 = fmaxf(c[mt][nt][2] + b1s[col], 0.f);
            float v3 = fmaxf(c[mt][nt][3] + b1s[col + 1], 0.f);
            h1s[row][col2]     = f2bf16x2(v0, v1);
            h1s[row + 8][col2] = f2bf16x2(v2, v3);
        }

    // ---- GEMM2: h2 = relu(h1 @ W2^T + b2), K=128 in 4 chunks of 32 ----------
#pragma unroll
    for (int mt = 0; mt < 2; ++mt)
#pragma unroll
        for (int nt = 0; nt < 4; ++nt)
#pragma unroll
            for (int i = 0; i < 4; ++i) c[mt][nt][i] = 0.f;

    for (int kt2 = 0; kt2 < 4; ++kt2) {
        const int k0 = kt2 * 32;
        float4 w0 = *(const float4*)(W2 + (size_t)lrowB * H + k0 + lkB);
        float4 w1 = *(const float4*)(W2 + (size_t)lrowB * H + k0 + lkB + 4);
        float4 w2 = *(const float4*)(W2 + (size_t)lrowB * H + k0 + lkB + 8);
        float4 w3 = *(const float4*)(W2 + (size_t)lrowB * H + k0 + lkB + 12);
        __syncthreads();   // prev chunk's W2s reads done (and h1s writes visible)
        *(uint4*)&W2s[lrowB][lkB2]     = cvt8(w0, w1);
        *(uint4*)&W2s[lrowB][lkB2 + 4] = cvt8(w2, w3);
        __syncthreads();
#pragma unroll
        for (int ks = 0; ks < 2; ++ks) {
            const int kb  = ks * 8;            // within W2s chunk (u32)
            const int kh  = kt2 * 16 + kb;     // within h1s (absolute, u32)
            uint32_t a[2][4], bf[4][2];
#pragma unroll
            for (int mt = 0; mt < 2; ++mt) {
                const int m = wm0 + mt * 16 + g;
                a[mt][0] = h1s[m][kh + tig];
                a[mt][1] = h1s[m + 8][kh + tig];
                a[mt][2] = h1s[m][kh + tig + 4];
                a[mt][3] = h1s[m + 8][kh + tig + 4];
            }
#pragma unroll
            for (int nt = 0; nt < 4; ++nt) {
                const int n = wn0 + nt * 8 + g;
                bf[nt][0] = W2s[n][kb + tig];
                bf[nt][1] = W2s[n][kb + tig + 4];
            }
#pragma unroll
            for (int mt = 0; mt < 2; ++mt)
#pragma unroll
                for (int nt = 0; nt < 4; ++nt) mma16(c[mt][nt], a[mt], bf[nt]);
        }
    }

    // ---- epilogue: h2 -> g_h2u (bf16x2) ------------------------------------
#pragma unroll
    for (int mt = 0; mt < 2; ++mt)
#pragma unroll
        for (int nt = 0; nt < 4; ++nt) {
            const int row  = wm0 + mt * 16 + g;
            const int col  = wn0 + nt * 8 + 2 * tig;
            const int col2 = col >> 1;
            float v0 = fmaxf(c[mt][nt][0] + b2s[col], 0.f);
            float v1 = fmaxf(c[mt][nt][1] + b2s[col + 1], 0.f);
            float v2 = fmaxf(c[mt][nt][2] + b2s[col], 0.f);
            float v3 = fmaxf(c[mt][nt][3] + b2s[col + 1], 0.f);
            g_h2u[(size_t)(bm0 + row) * (H / 2) + col2]     = f2bf16x2(v0, v1);
            g_h2u[(size_t)(bm0 + row + 8) * (H / 2) + col2] = f2bf16x2(v2, v3);
        }
}

// ---------------------------------------------------------------------------
// Fused front kernel: blocks 0..31 run AR (256 rows each, 1 row/thread),
// blocks 32..159 run the MLP front. Independent outputs; co-resident on chip
// so the low-occupancy AR hides under the tensor-bound MLP.
// ---------------------------------------------------------------------------
__global__ __launch_bounds__(256) void front_kernel(const float* __restrict__ x,
                                                    const float* __restrict__ noise,
                                                    const float* __restrict__ W1,
                                                    const float* __restrict__ b1,
                                                    const float* __restrict__ W2,
                                                    const float* __restrict__ b2,
                                                    const float* __restrict__ coef,
                                                    float* __restrict__ out) {
    __shared__ __align__(16) unsigned char smem_raw[41984];
    if (blockIdx.x < 32) {
        ar_row(noise, coef, out, blockIdx.x * 256 + threadIdx.x);
    } else {
        mlp12_body(smem_raw, blockIdx.x - 32, x, W1, b1, W2, b2);
    }
}

// ---------------------------------------------------------------------------
// Kernel 3: out = tanh(h2 @ W3^T + b3) + out   (out already holds AR)
// M=8192, N=4096, K=128, BK=32 (4 iters). BM=BN=128, 2048 blocks.
// Warp tile 64x32 (MT=4, NT=4). A is already bf16 (g_h2u).
// ---------------------------------------------------------------------------
__global__ __launch_bounds__(256) void gemm3_kernel(const float* __restrict__ W3,
                                                    const float* __restrict__ b3,
                                                    float* __restrict__ out) {
    __shared__ __align__(16) uint32_t As3[2][128][20];
    __shared__ __align__(16) uint32_t Bs3[2][128][20];
    __shared__ float b3s[128];

    const int tid  = threadIdx.x;
    const int warp = tid >> 5, lane = tid & 31;
    const int g    = lane >> 2, tig = lane & 3;
    const int wm0  = (warp >> 2) * 64;   // 0 or 64
    const int wn0  = (warp & 3) * 32;    // 0,32,64,96
    const int bm0  = blockIdx.y * 128;
    const int bn0  = blockIdx.x * 128;

    if (tid < 128) b3s[tid] = b3[bn0 + tid];

    const int lrow = tid >> 1;            // 0..127
    const int lkE  = (tid & 1) * 16;      // element offset (of 32)
    const int lk2  = lkE >> 1;            // u32 offset (0 or 8)

    const uint32_t* gA = g_h2u + (size_t)(bm0 + lrow) * (H / 2) + lk2;
    const float*    gB = W3 + (size_t)(bn0 + lrow) * H + lkE;

    float c[4][4][4];
#pragma unroll
    for (int mt = 0; mt < 4; ++mt)
#pragma unroll
        for (int nt = 0; nt < 4; ++nt)
#pragma unroll
            for (int i = 0; i < 4; ++i) c[mt][nt][i] = 0.f;

    {
        uint4  a0 = *(const uint4*)gA;
        uint4  a1 = *(const uint4*)(gA + 4);
        float4 w0 = *(const float4*)gB;
        float4 w1 = *(const float4*)(gB + 4);
        float4 w2 = *(const float4*)(gB + 8);
        float4 w3 = *(const float4*)(gB + 12);
        *(uint4*)&As3[0][lrow][lk2]     = a0;
        *(uint4*)&As3[0][lrow][lk2 + 4] = a1;
        *(uint4*)&Bs3[0][lrow][lk2]     = cvt8(w0, w1);
        *(uint4*)&Bs3[0][lrow][lk2 + 4] = cvt8(w2, w3);
    }
    __syncthreads();

    for (int kt = 0; kt < 4; ++kt) {
        const int cur = kt & 1;
        uint4 a0, a1; float4 w0, w1, w2, w3;
        if (kt + 1 < 4) {
            a0 = *(const uint4*)(gA + (kt + 1) * 16);
            a1 = *(const uint4*)(gA + (kt + 1) * 16 + 4);
            const float* gBo = gB + (kt + 1) * 32;
            w0 = *(const float4*)gBo;
            w1 = *(const float4*)(gBo + 4);
            w2 = *(const float4*)(gBo + 8);
            w3 = *(const float4*)(gBo + 12);
        }
#pragma unroll
        for (int ks = 0; ks < 2; ++ks) {
            const int kb = ks * 8;
            uint32_t a[4][4], bf[4][2];
#pragma unroll
            for (int mt = 0; mt < 4; ++mt) {
                const int m = wm0 + mt * 16 + g;
                a[mt][0] = As3[cur][m][kb + tig];
                a[mt][1] = As3[cur][m + 8][kb + tig];
                a[mt][2] = As3[cur][m][kb + tig + 4];
                a[mt][3] = As3[cur][m + 8][kb + tig + 4];
            }
#pragma unroll
            for (int nt = 0; nt < 4; ++nt) {
                const int n = wn0 + nt * 8 + g;
                bf[nt][0] = Bs3[cur][n][kb + tig];
                bf[nt][1] = Bs3[cur][n][kb + tig + 4];
            }
#pragma unroll
            for (int mt = 0; mt < 4; ++mt)
#pragma unroll
                for (int nt = 0; nt < 4; ++nt) mma16(c[mt][nt], a[mt], bf[nt]);
        }
        if (kt + 1 < 4) {
            const int nb = cur ^ 1;
            *(uint4*)&As3[nb][lrow][lk2]     = a0;
            *(uint4*)&As3[nb][lrow][lk2 + 4] = a1;
            *(uint4*)&Bs3[nb][lrow][lk2]     = cvt8(w0, w1);
            *(uint4*)&Bs3[nb][lrow][lk2 + 4] = cvt8(w2, w3);
        }
        __syncthreads();
    }

    // epilogue: tanh(acc + b3) + ar (RMW d_out)
#pragma unroll
    for (int mt = 0; mt < 4; ++mt)
#pragma unroll
        for (int nt = 0; nt < 4; ++nt) {
            const int row = wm0 + mt * 16 + g;
            const int col = wn0 + nt * 8 + 2 * tig;
            size_t o0 = (size_t)(bm0 + row) * S_OUT + bn0 + col;
            float2 ar0 = *(float2*)&out[o0];
            float2 r0;
            r0.x = tanhf(c[mt][nt][0] + b3s[col]) + ar0.x;
            r0.y = tanhf(c[mt][nt][1] + b3s[col + 1]) + ar0.y;
            *(float2*)&out[o0] = r0;
            size_t o1 = o0 + (size_t)8 * S_OUT;
            float2 ar1 = *(float2*)&out[o1];
            float2 r1;
            r1.x = tanhf(c[mt][nt][2] + b3s[col]) + ar1.x;
            r1.y = tanhf(c[mt][nt][3] + b3s[col + 1]) + ar1.y;
            *(float2*)&out[o1] = r1;
        }
}

// ---------------------------------------------------------------------------
// Inputs (metadata order): x, noise, W1, b1, W2, b2, W3, b3, ar_coef
// ---------------------------------------------------------------------------
extern "C" void kernel_launch(void* const* d_in, const int* in_sizes, int n_in,
                              void* d_out, int out_size) {
    const float* x     = (const float*)d_in[0];
    const float* noise = (const float*)d_in[1];
    const float* W1    = (const float*)d_in[2];
    const float* b1    = (const float*)d_in[3];
    const float* W2    = (const float*)d_in[4];
    const float* b2    = (const float*)d_in[5];
    const float* W3    = (const float*)d_in[6];
    const float* b3    = (const float*)d_in[7];
    const float* arc   = (const float*)d_in[8];
    float* out = (float*)d_out;

    front_kernel<<<160, 256>>>(x, noise, W1, b1, W2, b2, arc, out);
    gemm3_kernel<<<dim3(32, 64), 256>>>(W3, b3, out);
}